// round 15
// baseline (speedup 1.0000x reference)
#include <cuda_runtime.h>
#include <cstdint>

// Uniform cubic B-spline, convert-free Horner via magic-number floor.
// t = (x+1)*31.5 in [0,63). d0 = t-0.5; r = RN(d0 + 1.5*2^23) gives
// kf = floor(t) (knot-ties land on the neighboring interval, where the C2
// spline's cubics agree to fp rounding). e = d0-kf in [-0.5,0.5] (exact).
// idx = low mantissa bits of r. Table holds q(e) = p(e+0.5), the interval
// monomial Taylor-shifted by +0.5:
//   p0=(c0+4c1+c2)/6, p1=(c2-c0)/2, p2=(c0-2c1+c2)/2, p3=(c3-c0+3(c1-c2))/6
//   q3=p3, q2=p2+1.5p3, q1=p1+p2+0.75p3, q0=p0+0.5p1+0.25p2+0.125p3
// 8-way bank-group replication -> conflict-free LDS.128 gathers.
// R15 = R13 shape (1024 CTAs x 512 thr, 2 x 8KB TMA chunks) with TMA issued
// BEFORE the table build (fill hides behind prologue) + zero-XU eval.

#define REP   8
#define NTBL  64
#define CHUNK 512                    // float4 per chunk (8KB)
#define MAGIC 12582912.0f            // 1.5 * 2^23

__device__ __forceinline__ uint32_t smem_u32(const void* p) {
    return (uint32_t)__cvta_generic_to_shared(p);
}
__device__ __forceinline__ void mbar_init(uint32_t mbar, uint32_t count) {
    asm volatile("mbarrier.init.shared.b64 [%0], %1;" :: "r"(mbar), "r"(count) : "memory");
}
__device__ __forceinline__ void fence_proxy_async_cta() {
    asm volatile("fence.proxy.async.shared::cta;" ::: "memory");
}
__device__ __forceinline__ void mbar_expect_tx(uint32_t mbar, uint32_t bytes) {
    asm volatile("mbarrier.arrive.expect_tx.shared.b64 _, [%0], %1;"
                 :: "r"(mbar), "r"(bytes) : "memory");
}
__device__ __forceinline__ void bulk_g2s(uint32_t dst, const void* src,
                                         uint32_t bytes, uint32_t mbar) {
    asm volatile("cp.async.bulk.shared::cta.global.mbarrier::complete_tx::bytes "
                 "[%0], [%1], %2, [%3];"
                 :: "r"(dst), "l"(src), "r"(bytes), "r"(mbar) : "memory");
}
__device__ __forceinline__ void mbar_wait(uint32_t mbar, uint32_t parity) {
    asm volatile(
        "{\n\t"
        ".reg .pred P;\n\t"
        "WAIT_%=: \n\t"
        "mbarrier.try_wait.parity.acquire.cta.shared::cta.b64 P, [%0], %1, 0x989680;\n\t"
        "@P bra.uni DONE_%=;\n\t"
        "bra.uni WAIT_%=;\n\t"
        "DONE_%=: \n\t"
        "}"
        :: "r"(mbar), "r"(parity) : "memory");
}

__device__ __forceinline__ float eval_one(float x, const float4* __restrict__ tp) {
    float d0 = fmaf(x, 31.5f, 31.0f);          // t - 0.5, t in [0,63)
    float r  = __fadd_rn(d0, MAGIC);           // RN -> kf = floor(t)
    float kf = __fadd_rn(r, -MAGIC);
    float e  = d0 - kf;                        // in [-0.5, 0.5], exact
    int idx  = __float_as_int(r) & 63;         // low mantissa bits = kf
    float4 q = tp[idx * REP];                  // tp pre-offset by bank-group
    return fmaf(fmaf(fmaf(q.w, e, q.z), e, q.y), e, q.x);
}

__device__ __forceinline__ float4 eval_four(float4 xv, const float4* __restrict__ tp) {
    float4 ov;
    ov.x = eval_one(xv.x, tp);
    ov.y = eval_one(xv.y, tp);
    ov.z = eval_one(xv.z, tp);
    ov.w = eval_one(xv.w, tp);
    return ov;
}

__global__ void __launch_bounds__(512, 4)
bspline_kernel(const float4* __restrict__ x4,
               const float* __restrict__ coeffs,
               float4* __restrict__ o4, int n4) {
    __shared__ float4 tbl[NTBL * REP];               // 8 KB
    __shared__ float4 xbuf[2][CHUNK];                // 16 KB
    __shared__ __align__(8) unsigned long long mbar_s[2];
    int tid = threadIdx.x;

    int base = blockIdx.x * (2 * CHUNK);
    int rem  = n4 - base;
    int cnt0 = min(rem, CHUNK);
    int cnt1 = min(max(rem - CHUNK, 0), CHUNK);

    uint32_t mb0 = smem_u32(&mbar_s[0]);
    uint32_t mb1 = smem_u32(&mbar_s[1]);

    // TMAs FIRST: fill latency hides behind the table build.
    if (tid == 0) {
        mbar_init(mb0, 1);
        mbar_init(mb1, 1);
        fence_proxy_async_cta();
        mbar_expect_tx(mb0, (uint32_t)cnt0 * 16u);
        bulk_g2s(smem_u32(&xbuf[0][0]), x4 + base, (uint32_t)cnt0 * 16u, mb0);
        if (cnt1 > 0) {
            mbar_expect_tx(mb1, (uint32_t)cnt1 * 16u);
            bulk_g2s(smem_u32(&xbuf[1][0]), x4 + base + CHUNK,
                     (uint32_t)cnt1 * 16u, mb1);
        }
    }

    // Table build overlaps the fill: one shifted-monomial entry per thread.
    {
        int j = min(tid >> 3, 62);       // entry 63 duplicates interval 62
        float c0 = __ldg(coeffs + j);
        float c1 = __ldg(coeffs + j + 1);
        float c2 = __ldg(coeffs + j + 2);
        float c3 = __ldg(coeffs + j + 3);
        float p0 = fmaf(4.0f, c1, c0 + c2) * 0.16666666666666666f;
        float p1 = (c2 - c0) * 0.5f;
        float p2 = fmaf(-2.0f, c1, c0 + c2) * 0.5f;
        float p3 = fmaf(3.0f, c1 - c2, c3 - c0) * 0.16666666666666666f;
        float4 q;
        q.w = p3;
        q.z = fmaf(1.5f, p3, p2);
        q.y = fmaf(0.75f, p3, p1 + p2);
        q.x = fmaf(0.5f, p1, fmaf(0.25f, p2, fmaf(0.125f, p3, p0)));
        tbl[tid] = q;
    }
    __syncthreads();                     // table + mbar init visible

    const float4* __restrict__ tp = tbl + (tid & (REP - 1));

    mbar_wait(mb0, 0);
    if (tid < cnt0) {
        float4 xv = xbuf[0][tid];
        o4[base + tid] = eval_four(xv, tp);
    }
    if (cnt1 > 0) {
        mbar_wait(mb1, 0);
        if (tid < cnt1) {
            float4 xv = xbuf[1][tid];
            o4[base + CHUNK + tid] = eval_four(xv, tp);
        }
    }
}

extern "C" void kernel_launch(void* const* d_in, const int* in_sizes, int n_in,
                              void* d_out, int out_size) {
    const float* x      = (const float*)d_in[0];
    const float* coeffs = (const float*)d_in[1];
    float* out = (float*)d_out;
    int n  = in_sizes[0];
    int n4 = n >> 2;                           // N = 2^22 -> n4 = 2^20
    int threads = 512;
    int blocks  = (n4 + 2 * CHUNK - 1) / (2 * CHUNK);   // 1024 for N=2^22
    if (blocks < 1) blocks = 1;
    bspline_kernel<<<blocks, threads>>>((const float4*)x, coeffs, (float4*)out, n4);
}

// round 16
// speedup vs baseline: 1.2399x; 1.2399x over previous
#include <cuda_runtime.h>
#include <cstdint>

// Uniform cubic B-spline via per-interval monomial (Horner) form.
// t = (x+1)*31.5 in [0,63], j = trunc(t), u = t-j,
// out = p0[j] + u*(p1[j] + u*(p2[j] + u*p3[j])), with
//   p0=(c0+4c1+c2)/6, p1=(c2-c0)/2, p2=(c0-2c1+c2)/2, p3=(c3-c0+3(c1-c2))/6.
// Table padded to 64 entries (entry 63 dups interval 62) -> no clamp.
// 8-way bank-group replication -> conflict-free LDS.128 gathers.
//
// R16 = R13 (best: 1024 CTAs x 512 thr, 2 x 8KB cp.async.bulk chunks, F2I
// eval) + the TMA-first prologue ordering: thread 0 inits mbarriers and
// issues both bulk fills BEFORE the table build, so chunk-0 fill latency
// hides behind the prologue instead of following it.

#define REP   8
#define NTBL  64
#define CHUNK 512                    // float4 per chunk (8KB)

__device__ __forceinline__ uint32_t smem_u32(const void* p) {
    return (uint32_t)__cvta_generic_to_shared(p);
}
__device__ __forceinline__ void mbar_init(uint32_t mbar, uint32_t count) {
    asm volatile("mbarrier.init.shared.b64 [%0], %1;" :: "r"(mbar), "r"(count) : "memory");
}
__device__ __forceinline__ void fence_proxy_async_cta() {
    asm volatile("fence.proxy.async.shared::cta;" ::: "memory");
}
__device__ __forceinline__ void mbar_expect_tx(uint32_t mbar, uint32_t bytes) {
    asm volatile("mbarrier.arrive.expect_tx.shared.b64 _, [%0], %1;"
                 :: "r"(mbar), "r"(bytes) : "memory");
}
__device__ __forceinline__ void bulk_g2s(uint32_t dst, const void* src,
                                         uint32_t bytes, uint32_t mbar) {
    asm volatile("cp.async.bulk.shared::cta.global.mbarrier::complete_tx::bytes "
                 "[%0], [%1], %2, [%3];"
                 :: "r"(dst), "l"(src), "r"(bytes), "r"(mbar) : "memory");
}
__device__ __forceinline__ void mbar_wait(uint32_t mbar, uint32_t parity) {
    asm volatile(
        "{\n\t"
        ".reg .pred P;\n\t"
        "WAIT_%=: \n\t"
        "mbarrier.try_wait.parity.acquire.cta.shared::cta.b64 P, [%0], %1, 0x989680;\n\t"
        "@P bra.uni DONE_%=;\n\t"
        "bra.uni WAIT_%=;\n\t"
        "DONE_%=: \n\t"
        "}"
        :: "r"(mbar), "r"(parity) : "memory");
}

__device__ __forceinline__ float eval_one(float x, const float4* __restrict__ tp) {
    float t = fmaf(x, 31.5f, 31.5f);     // in [0, 63]
    int j = (int)t;                      // trunc == floor; table padded to 64
    float u = t - (float)j;
    float4 p = tp[j * REP];              // tp pre-offset by lane's bank-group
    return fmaf(fmaf(fmaf(p.w, u, p.z), u, p.y), u, p.x);
}

__device__ __forceinline__ float4 eval_four(float4 xv, const float4* __restrict__ tp) {
    float4 ov;
    ov.x = eval_one(xv.x, tp);
    ov.y = eval_one(xv.y, tp);
    ov.z = eval_one(xv.z, tp);
    ov.w = eval_one(xv.w, tp);
    return ov;
}

__global__ void __launch_bounds__(512, 4)
bspline_kernel(const float4* __restrict__ x4,
               const float* __restrict__ coeffs,
               float4* __restrict__ o4, int n4) {
    __shared__ float4 tbl[NTBL * REP];               // 8 KB
    __shared__ float4 xbuf[2][CHUNK];                // 16 KB
    __shared__ __align__(8) unsigned long long mbar_s[2];
    int tid = threadIdx.x;

    int base = blockIdx.x * (2 * CHUNK);
    int rem  = n4 - base;
    int cnt0 = min(rem, CHUNK);
    int cnt1 = min(max(rem - CHUNK, 0), CHUNK);

    uint32_t mb0 = smem_u32(&mbar_s[0]);
    uint32_t mb1 = smem_u32(&mbar_s[1]);

    // TMAs first: chunk-0 fill latency hides behind the table build.
    if (tid == 0) {
        mbar_init(mb0, 1);
        mbar_init(mb1, 1);
        fence_proxy_async_cta();
        mbar_expect_tx(mb0, (uint32_t)cnt0 * 16u);
        bulk_g2s(smem_u32(&xbuf[0][0]), x4 + base, (uint32_t)cnt0 * 16u, mb0);
        if (cnt1 > 0) {
            mbar_expect_tx(mb1, (uint32_t)cnt1 * 16u);
            bulk_g2s(smem_u32(&xbuf[1][0]), x4 + base + CHUNK,
                     (uint32_t)cnt1 * 16u, mb1);
        }
    }

    // Table build overlaps the fill: one monomial entry per thread.
    {
        int j = min(tid >> 3, 62);       // entry 63 duplicates interval 62
        float c0 = __ldg(coeffs + j);
        float c1 = __ldg(coeffs + j + 1);
        float c2 = __ldg(coeffs + j + 2);
        float c3 = __ldg(coeffs + j + 3);
        float4 p;
        p.x = fmaf(4.0f, c1, c0 + c2) * 0.16666666666666666f;
        p.y = (c2 - c0) * 0.5f;
        p.z = fmaf(-2.0f, c1, c0 + c2) * 0.5f;
        p.w = fmaf(3.0f, c1 - c2, c3 - c0) * 0.16666666666666666f;
        tbl[tid] = p;
    }
    __syncthreads();                     // table + mbar init visible

    const float4* __restrict__ tp = tbl + (tid & (REP - 1));

    mbar_wait(mb0, 0);
    if (tid < cnt0) {
        float4 xv = xbuf[0][tid];
        o4[base + tid] = eval_four(xv, tp);
    }
    if (cnt1 > 0) {
        mbar_wait(mb1, 0);
        if (tid < cnt1) {
            float4 xv = xbuf[1][tid];
            o4[base + CHUNK + tid] = eval_four(xv, tp);
        }
    }
}

extern "C" void kernel_launch(void* const* d_in, const int* in_sizes, int n_in,
                              void* d_out, int out_size) {
    const float* x      = (const float*)d_in[0];
    const float* coeffs = (const float*)d_in[1];
    float* out = (float*)d_out;
    int n  = in_sizes[0];
    int n4 = n >> 2;                           // N = 2^22 -> n4 = 2^20
    int threads = 512;
    int blocks  = (n4 + 2 * CHUNK - 1) / (2 * CHUNK);   // 1024 for N=2^22
    if (blocks < 1) blocks = 1;
    bspline_kernel<<<blocks, threads>>>((const float4*)x, coeffs, (float4*)out, n4);
}